// round 1
// baseline (speedup 1.0000x reference)
#include <cuda_runtime.h>
#include <math_constants.h>

#define H 1024
#define S 32768
#define NBLK_SCORES (S / 8)      // 4096 blocks, 8 rows (warps) per block
#define D_SLICES 32              // partial-sum slices over the d dimension of W

// Scratch (no allocations allowed)
__device__ float g_vpart[D_SLICES * H];
__device__ float g_v[H];
__device__ float g_c;
__device__ float g_scores[S];
__device__ float g_bmax[NBLK_SCORES];

// ---------------------------------------------------------------------------
// K1: partial v[h] = sum over a 32-wide slice of d of W[d][h] * hidden[d]
// grid (H/256, D_SLICES), block 256.  Coalesced reads of W rows.
// ---------------------------------------------------------------------------
__global__ void v_partial_kernel(const float* __restrict__ W,
                                 const float* __restrict__ hidden) {
    const int h  = blockIdx.x * 256 + threadIdx.x;
    const int d0 = blockIdx.y * (H / D_SLICES);
    float acc = 0.f;
#pragma unroll
    for (int dd = 0; dd < H / D_SLICES; dd++) {
        acc += W[(size_t)(d0 + dd) * H + h] * __ldg(&hidden[d0 + dd]);
    }
    g_vpart[blockIdx.y * H + h] = acc;
}

// ---------------------------------------------------------------------------
// K2: reduce partials -> g_v ; one extra block computes c = b . hidden
// grid (H/256 + 1), block 256.
// ---------------------------------------------------------------------------
__global__ void v_reduce_kernel(const float* __restrict__ b,
                                const float* __restrict__ hidden) {
    if (blockIdx.x < H / 256) {
        const int h = blockIdx.x * 256 + threadIdx.x;
        float acc = 0.f;
#pragma unroll
        for (int i = 0; i < D_SLICES; i++) acc += g_vpart[i * H + h];
        g_v[h] = acc;
    } else {
        // c = dot(b, hidden)
        __shared__ float red[256];
        float acc = 0.f;
        for (int i = threadIdx.x; i < H; i += 256) acc += b[i] * hidden[i];
        red[threadIdx.x] = acc;
        __syncthreads();
        for (int s = 128; s > 0; s >>= 1) {
            if (threadIdx.x < s) red[threadIdx.x] += red[threadIdx.x + s];
            __syncthreads();
        }
        if (threadIdx.x == 0) g_c = red[0];
    }
}

// ---------------------------------------------------------------------------
// K3: scores[s] = enc[s] . v + c     (the 128 MB streaming kernel)
// One warp per row; 8 rows per 256-thread block. float4 loads, 8 indep per lane.
// Also computes per-block max -> g_bmax.
// ---------------------------------------------------------------------------
__global__ __launch_bounds__(256) void scores_kernel(const float* __restrict__ enc) {
    __shared__ float sv[H];
    __shared__ float smax[8];

    // stage v into shared (256 threads x float4)
    reinterpret_cast<float4*>(sv)[threadIdx.x] =
        reinterpret_cast<const float4*>(g_v)[threadIdx.x];
    __syncthreads();

    const int warp = threadIdx.x >> 5;
    const int lane = threadIdx.x & 31;
    const size_t row = (size_t)blockIdx.x * 8 + warp;

    const float4* r = reinterpret_cast<const float4*>(enc + row * H);
    const float4* v4 = reinterpret_cast<const float4*>(sv);

    float acc = 0.f;
#pragma unroll
    for (int k = 0; k < 8; k++) {
        float4 e  = r[lane + k * 32];
        float4 vv = v4[lane + k * 32];
        acc += e.x * vv.x + e.y * vv.y + e.z * vv.z + e.w * vv.w;
    }
#pragma unroll
    for (int o = 16; o > 0; o >>= 1) acc += __shfl_xor_sync(0xFFFFFFFFu, acc, o);

    if (lane == 0) {
        float score = acc + g_c;
        g_scores[row] = score;
        smax[warp] = score;
    }
    __syncthreads();
    if (threadIdx.x == 0) {
        float m = smax[0];
#pragma unroll
        for (int i = 1; i < 8; i++) m = fmaxf(m, smax[i]);
        g_bmax[blockIdx.x] = m;
    }
}

// ---------------------------------------------------------------------------
// K4: single-block softmax over the 32768 scores (L2-resident).
// 1024 threads, 32 values each held in registers.
// ---------------------------------------------------------------------------
__global__ __launch_bounds__(1024) void softmax_kernel(float* __restrict__ out) {
    __shared__ float red[1024];
    const int tid = threadIdx.x;

    // global max over block maxima
    float m = -CUDART_INF_F;
#pragma unroll
    for (int i = tid; i < NBLK_SCORES; i += 1024) m = fmaxf(m, g_bmax[i]);
    red[tid] = m;
    __syncthreads();
    for (int s = 512; s > 0; s >>= 1) {
        if (tid < s) red[tid] = fmaxf(red[tid], red[tid + s]);
        __syncthreads();
    }
    const float gmax = red[0];
    __syncthreads();

    // exp + sum, values kept in registers
    float e[S / 1024];
    float sum = 0.f;
#pragma unroll
    for (int k = 0; k < S / 1024; k++) {
        float v = expf(g_scores[tid + k * 1024] - gmax);
        e[k] = v;
        sum += v;
    }
    red[tid] = sum;
    __syncthreads();
    for (int s = 512; s > 0; s >>= 1) {
        if (tid < s) red[tid] += red[tid + s];
        __syncthreads();
    }
    const float inv = 1.0f / red[0];

#pragma unroll
    for (int k = 0; k < S / 1024; k++) out[tid + k * 1024] = e[k] * inv;
}

// ---------------------------------------------------------------------------
extern "C" void kernel_launch(void* const* d_in, const int* in_sizes, int n_in,
                              void* d_out, int out_size) {
    const float* hidden = (const float*)d_in[0];   // [H]
    const float* enc    = (const float*)d_in[1];   // [S, H]
    const float* W      = (const float*)d_in[2];   // [H, H]
    const float* b      = (const float*)d_in[3];   // [H]
    float* out          = (float*)d_out;           // [S]

    v_partial_kernel<<<dim3(H / 256, D_SLICES), 256>>>(W, hidden);
    v_reduce_kernel<<<H / 256 + 1, 256>>>(b, hidden);
    scores_kernel<<<NBLK_SCORES, 256>>>(enc);
    softmax_kernel<<<1, 1024>>>(out);
}

// round 2
// speedup vs baseline: 1.0638x; 1.0638x over previous
#include <cuda_runtime.h>
#include <math_constants.h>

#define H 1024
#define S 32768
#define ROWS_PER_BLK 8
#define NBLK_SCORES (S / ROWS_PER_BLK)   // 4096
#define D_SLICES 64                      // 16 d-rows per slice

// Scratch (no allocations allowed)
__device__ float g_vpart[D_SLICES * H];
__device__ float g_v[H];
__device__ float g_scores[S];
__device__ float g_bmax[NBLK_SCORES];
__device__ float g_bsum[NBLK_SCORES];
__device__ float g_M;
__device__ float g_inv;

// ---------------------------------------------------------------------------
// K1: partial v[h] = sum over a 16-wide slice of d of W[d][h] * hidden[d]
// grid (H/256=4, D_SLICES=64), block 256. Coalesced reads of W rows.
// ---------------------------------------------------------------------------
__global__ void v_partial_kernel(const float* __restrict__ W,
                                 const float* __restrict__ hidden) {
    const int h  = blockIdx.x * 256 + threadIdx.x;
    const int d0 = blockIdx.y * (H / D_SLICES);
    float acc = 0.f;
#pragma unroll
    for (int dd = 0; dd < H / D_SLICES; dd++) {
        acc += W[(size_t)(d0 + dd) * H + h] * __ldg(&hidden[d0 + dd]);
    }
    g_vpart[blockIdx.y * H + h] = acc;
}

// ---------------------------------------------------------------------------
// K2: reduce partials -> g_v.  grid 4, block 256.
// (bias b is dropped: softmax is shift-invariant, b.hidden is a constant)
// ---------------------------------------------------------------------------
__global__ void v_reduce_kernel() {
    const int h = blockIdx.x * 256 + threadIdx.x;
    float acc = 0.f;
#pragma unroll
    for (int i = 0; i < D_SLICES; i++) acc += g_vpart[i * H + h];
    g_v[h] = acc;
}

// ---------------------------------------------------------------------------
// K3: scores[s] = enc[s] . v     (the 128 MB streaming kernel)
// One warp per row; 8 rows per 256-thread block. float4 loads.
// Emits per-block max m_b and per-block expsum S_b = sum exp(s - m_b).
// ---------------------------------------------------------------------------
__global__ __launch_bounds__(256) void scores_kernel(const float* __restrict__ enc) {
    __shared__ float sv[H];
    __shared__ float s_sc[ROWS_PER_BLK];

    reinterpret_cast<float4*>(sv)[threadIdx.x] =
        reinterpret_cast<const float4*>(g_v)[threadIdx.x];
    __syncthreads();

    const int warp = threadIdx.x >> 5;
    const int lane = threadIdx.x & 31;
    const size_t row = (size_t)blockIdx.x * ROWS_PER_BLK + warp;

    const float4* r  = reinterpret_cast<const float4*>(enc + row * H);
    const float4* v4 = reinterpret_cast<const float4*>(sv);

    float acc = 0.f;
#pragma unroll
    for (int k = 0; k < 8; k++) {
        float4 e  = r[lane + k * 32];
        float4 vv = v4[lane + k * 32];
        acc += e.x * vv.x + e.y * vv.y + e.z * vv.z + e.w * vv.w;
    }
#pragma unroll
    for (int o = 16; o > 0; o >>= 1) acc += __shfl_xor_sync(0xFFFFFFFFu, acc, o);

    if (lane == 0) {
        g_scores[row] = acc;
        s_sc[warp] = acc;
    }
    __syncthreads();
    if (threadIdx.x == 0) {
        float m = s_sc[0];
#pragma unroll
        for (int i = 1; i < ROWS_PER_BLK; i++) m = fmaxf(m, s_sc[i]);
        float sum = 0.f;
#pragma unroll
        for (int i = 0; i < ROWS_PER_BLK; i++) sum += __expf(s_sc[i] - m);
        g_bmax[blockIdx.x] = m;
        g_bsum[blockIdx.x] = sum;
    }
}

// ---------------------------------------------------------------------------
// K4: reduce (m_b, S_b) pairs -> global max M and inv = 1/total.
// 1 block, 1024 threads, 4 pairs per thread (8K floats total, L2-resident).
// ---------------------------------------------------------------------------
__global__ __launch_bounds__(1024) void softmax_reduce_kernel() {
    __shared__ float red[1024];
    const int tid = threadIdx.x;

    float m = -CUDART_INF_F;
#pragma unroll
    for (int k = 0; k < NBLK_SCORES / 1024; k++)
        m = fmaxf(m, g_bmax[tid + k * 1024]);
    red[tid] = m;
    __syncthreads();
    for (int s = 512; s > 0; s >>= 1) {
        if (tid < s) red[tid] = fmaxf(red[tid], red[tid + s]);
        __syncthreads();
    }
    const float M = red[0];
    __syncthreads();

    float sum = 0.f;
#pragma unroll
    for (int k = 0; k < NBLK_SCORES / 1024; k++) {
        int i = tid + k * 1024;
        sum += g_bsum[i] * __expf(g_bmax[i] - M);
    }
    red[tid] = sum;
    __syncthreads();
    for (int s = 512; s > 0; s >>= 1) {
        if (tid < s) red[tid] += red[tid + s];
        __syncthreads();
    }
    if (tid == 0) {
        g_M = M;
        g_inv = 1.0f / red[0];
    }
}

// ---------------------------------------------------------------------------
// K5: fully parallel normalize.  grid 128, block 256, 1 element/thread.
// ---------------------------------------------------------------------------
__global__ __launch_bounds__(256) void normalize_kernel(float* __restrict__ out) {
    const int i = blockIdx.x * 256 + threadIdx.x;
    const float M = g_M;
    const float inv = g_inv;
    out[i] = __expf(g_scores[i] - M) * inv;
}

// ---------------------------------------------------------------------------
extern "C" void kernel_launch(void* const* d_in, const int* in_sizes, int n_in,
                              void* d_out, int out_size) {
    const float* hidden = (const float*)d_in[0];   // [H]
    const float* enc    = (const float*)d_in[1];   // [S, H]
    const float* W      = (const float*)d_in[2];   // [H, H]
    float* out          = (float*)d_out;           // [S]

    v_partial_kernel<<<dim3(H / 256, D_SLICES), 256>>>(W, hidden);
    v_reduce_kernel<<<H / 256, 256>>>();
    scores_kernel<<<NBLK_SCORES, 256>>>(enc);
    softmax_reduce_kernel<<<1, 1024>>>();
    normalize_kernel<<<S / 256, 256>>>(out);
}